// round 8
// baseline (speedup 1.0000x reference)
#include <cuda_runtime.h>
#include <math.h>
#include <float.h>

#define BB    8
#define TT    1024
#define FF    256
#define NH    4
#define DKK   64
#define BHH   32
#define NROWS 8192

#define SSTR  1028   // Ss row stride in floats; 1028*4=4112 bytes = 16B-aligned

// ---------------- scratch ----------------------------------------------------
static __device__ float g_xn[NROWS * FF];
static __device__ float g_q [BHH * TT * DKK];
static __device__ float g_k [BHH * TT * DKK];
static __device__ float g_v [BHH * TT * DKK];
static __device__ float g_s [(size_t)BHH * TT * TT];
static __device__ float g_att[NROWS * FF];

// ---------------- helpers -----------------------------------------------------
__device__ __forceinline__ unsigned f2tf(float x) {
    unsigned r; asm("cvt.rna.tf32.f32 %0, %1;" : "=r"(r) : "f"(x)); return r;
}
__device__ __forceinline__ void mma8(float* d, const unsigned* a, const unsigned* b, const float* c) {
    asm volatile("mma.sync.aligned.m16n8k8.row.col.f32.tf32.tf32.f32 "
                 "{%0,%1,%2,%3}, {%4,%5,%6,%7}, {%8,%9}, {%10,%11,%12,%13};"
                 : "=f"(d[0]), "=f"(d[1]), "=f"(d[2]), "=f"(d[3])
                 : "r"(a[0]), "r"(a[1]), "r"(a[2]), "r"(a[3]),
                   "r"(b[0]), "r"(b[1]),
                   "f"(c[0]), "f"(c[1]), "f"(c[2]), "f"(c[3]));
}
__device__ __forceinline__ void cpa16(void* s, const void* g) {
    unsigned a = (unsigned)__cvta_generic_to_shared(s);
    asm volatile("cp.async.cg.shared.global [%0], [%1], 16;" :: "r"(a), "l"(g));
}
__device__ __forceinline__ void cp_commit() { asm volatile("cp.async.commit_group;"); }
template<int N> __device__ __forceinline__ void cp_wait() {
    asm volatile("cp.async.wait_group %0;" :: "n"(N));
}

// ---------------- 1) LayerNorm -----------------------------------------------
__global__ void ln_kernel(const float* __restrict__ x, const float* __restrict__ g,
                          const float* __restrict__ b, float* __restrict__ out)
{
    int row = blockIdx.x;
    int tid = threadIdx.x;
    float v = x[row * FF + tid];
    float s = v, sq = v * v;
    __shared__ float rs[8], rq[8];
    #pragma unroll
    for (int o = 16; o > 0; o >>= 1) {
        s  += __shfl_down_sync(0xffffffffu, s,  o);
        sq += __shfl_down_sync(0xffffffffu, sq, o);
    }
    if ((tid & 31) == 0) { rs[tid >> 5] = s; rq[tid >> 5] = sq; }
    __syncthreads();
    if (tid < 32) {
        float a = (tid < 8) ? rs[tid] : 0.f;
        float c = (tid < 8) ? rq[tid] : 0.f;
        #pragma unroll
        for (int o = 4; o > 0; o >>= 1) {
            a += __shfl_down_sync(0xffffffffu, a, o);
            c += __shfl_down_sync(0xffffffffu, c, o);
        }
        if (tid == 0) { rs[0] = a; rq[0] = c; }
    }
    __syncthreads();
    float mean = rs[0] * (1.f / FF);
    float var  = rq[0] * (1.f / FF) - mean * mean;
    float inv  = rsqrtf(fmaxf(var, 0.f) + 1e-5f);
    out[row * FF + tid] = (v - mean) * inv * g[tid] + b[tid];
}

// ---------------- 2) tf32 GEMM core: 128x64, BK=32, 3-stage cp.async ---------
#define G_STAGE_F (128 * 36 + 32 * 72)

__device__ __forceinline__ void gemm_body(
    const float* __restrict__ A, const float* __restrict__ W,
    const float* __restrict__ bias, float* __restrict__ C, int MODE)
{
    extern __shared__ float gsm[];
    int tid = threadIdx.x, w = tid >> 5, l = tid & 31, g = l >> 2, t4 = l & 3;
    int m0 = blockIdx.y * 128, n0 = blockIdx.x * 64;
    int wm = (w >> 1) * 32, wn = (w & 1) * 32;

    float acc[2][4][4];
    #pragma unroll
    for (int i = 0; i < 2; i++)
        #pragma unroll
        for (int j = 0; j < 4; j++)
            #pragma unroll
            for (int e = 0; e < 4; e++) acc[i][j][e] = 0.f;

    auto load_stage = [&](int s, int k0) {
        float* Ab = gsm + s * G_STAGE_F;
        float* Wb = Ab + 128 * 36;
        #pragma unroll
        for (int j = 0; j < 4; j++) {
            int ch = tid + 256 * j;
            int row = ch >> 3, c = ch & 7;
            cpa16(&Ab[row * 36 + c * 4], A + (size_t)(m0 + row) * FF + k0 + c * 4);
        }
        #pragma unroll
        for (int j = 0; j < 2; j++) {
            int ch = tid + 256 * j;
            int row = ch >> 4, c = ch & 15;
            cpa16(&Wb[row * 72 + c * 4], W + (size_t)(k0 + row) * FF + n0 + c * 4);
        }
        cp_commit();
    };

    load_stage(0, 0);
    load_stage(1, 32);

    for (int it = 0; it < 8; it++) {
        int s = it % 3;
        if (it == 7) cp_wait<0>(); else cp_wait<1>();
        __syncthreads();
        if (it + 2 < 8) load_stage((it + 2) % 3, (it + 2) * 32);
        const float* Ab = gsm + s * G_STAGE_F;
        const float* Wb = Ab + 128 * 36;
        #pragma unroll
        for (int ks = 0; ks < 4; ks++) {
            unsigned af[2][4], bf[4][2];
            #pragma unroll
            for (int mi = 0; mi < 2; mi++) {
                int r = wm + mi * 16;
                af[mi][0] = f2tf(Ab[(r + g    ) * 36 + ks * 8 + t4]);
                af[mi][1] = f2tf(Ab[(r + g + 8) * 36 + ks * 8 + t4]);
                af[mi][2] = f2tf(Ab[(r + g    ) * 36 + ks * 8 + t4 + 4]);
                af[mi][3] = f2tf(Ab[(r + g + 8) * 36 + ks * 8 + t4 + 4]);
            }
            #pragma unroll
            for (int ni = 0; ni < 4; ni++) {
                int c = wn + ni * 8 + g;
                bf[ni][0] = f2tf(Wb[(ks * 8 + t4    ) * 72 + c]);
                bf[ni][1] = f2tf(Wb[(ks * 8 + t4 + 4) * 72 + c]);
            }
            #pragma unroll
            for (int mi = 0; mi < 2; mi++)
                #pragma unroll
                for (int ni = 0; ni < 4; ni++)
                    mma8(acc[mi][ni], af[mi], bf[ni], acc[mi][ni]);
        }
        __syncthreads();
    }

    #pragma unroll
    for (int mi = 0; mi < 2; mi++) {
        #pragma unroll
        for (int ni = 0; ni < 4; ni++) {
            int col = n0 + wn + ni * 8 + 2 * t4;
            float b0 = bias[col], b1 = bias[col + 1];
            int r0 = m0 + wm + mi * 16 + g;
            float2 o0 = make_float2(acc[mi][ni][0] + b0, acc[mi][ni][1] + b1);
            float2 o1 = make_float2(acc[mi][ni][2] + b0, acc[mi][ni][3] + b1);
            if (MODE == 0) {
                int h = col >> 6, d = col & 63;
                int b_ = r0 >> 10, t = r0 & 1023;
                *(float2*)&C[(((size_t)(b_*NH + h) * TT + t) * DKK) + d] = o0;
                int r1 = r0 + 8; b_ = r1 >> 10; t = r1 & 1023;
                *(float2*)&C[(((size_t)(b_*NH + h) * TT + t) * DKK) + d] = o1;
            } else {
                *(float2*)&C[(size_t)r0 * FF + col] = o0;
                *(float2*)&C[(size_t)(r0 + 8) * FF + col] = o1;
            }
        }
    }
}

__global__ void __launch_bounds__(256)
proj3_kernel(const float* __restrict__ Aq, const float* __restrict__ Axn,
             const float* __restrict__ Wq, const float* __restrict__ bq,
             const float* __restrict__ Wk, const float* __restrict__ bk,
             const float* __restrict__ Wv, const float* __restrict__ bv,
             float* __restrict__ Cq, float* __restrict__ Ck, float* __restrict__ Cv)
{
    int z = blockIdx.z;
    const float* A = (z == 0) ? Aq : Axn;
    const float* W = (z == 0) ? Wq : (z == 1) ? Wk : Wv;
    const float* b = (z == 0) ? bq : (z == 1) ? bk : bv;
    float* C       = (z == 0) ? Cq : (z == 1) ? Ck : Cv;
    gemm_body(A, W, b, C, 0);
}

__global__ void __launch_bounds__(256)
gemm_out_kernel(const float* __restrict__ A, const float* __restrict__ W,
                const float* __restrict__ bias, float* __restrict__ C)
{
    gemm_body(A, W, bias, C, 1);
}

// ---------------- 3) tf32 QK^T: 128q x 128t, K=64 ----------------------------
__global__ void __launch_bounds__(256)
qk_tf32(const float* __restrict__ Q, const float* __restrict__ K, float* __restrict__ S)
{
    extern __shared__ float qksm[];
    float* Qs = qksm;             // [128][68]
    float* Ks = qksm + 128 * 68;  // [128][68]
    int tid = threadIdx.x, w = tid >> 5, l = tid & 31, g = l >> 2, t4 = l & 3;
    int bh = blockIdx.z, q0 = blockIdx.y * 128, t0 = blockIdx.x * 128;
    int wm = (w >> 2) * 64, wn = (w & 3) * 32;

    #pragma unroll
    for (int j = 0; j < 8; j++) {
        int ch = tid + 256 * j;
        int row = ch >> 4, c = ch & 15;
        cpa16(&Qs[row * 68 + c * 4], Q + ((size_t)bh * TT + q0 + row) * DKK + c * 4);
    }
    #pragma unroll
    for (int j = 0; j < 8; j++) {
        int ch = tid + 256 * j;
        int row = ch >> 4, c = ch & 15;
        cpa16(&Ks[row * 68 + c * 4], K + ((size_t)bh * TT + t0 + row) * DKK + c * 4);
    }
    cp_commit(); cp_wait<0>();
    __syncthreads();

    float acc[4][4][4];
    #pragma unroll
    for (int i = 0; i < 4; i++)
        #pragma unroll
        for (int j = 0; j < 4; j++)
            #pragma unroll
            for (int e = 0; e < 4; e++) acc[i][j][e] = 0.f;

    #pragma unroll
    for (int ks = 0; ks < 8; ks++) {
        unsigned af[4][4], bf[4][2];
        #pragma unroll
        for (int mi = 0; mi < 4; mi++) {
            int r = wm + mi * 16;
            af[mi][0] = f2tf(Qs[(r + g    ) * 68 + ks * 8 + t4]);
            af[mi][1] = f2tf(Qs[(r + g + 8) * 68 + ks * 8 + t4]);
            af[mi][2] = f2tf(Qs[(r + g    ) * 68 + ks * 8 + t4 + 4]);
            af[mi][3] = f2tf(Qs[(r + g + 8) * 68 + ks * 8 + t4 + 4]);
        }
        #pragma unroll
        for (int ni = 0; ni < 4; ni++) {
            int c = wn + ni * 8 + g;
            bf[ni][0] = f2tf(Ks[c * 68 + ks * 8 + t4]);
            bf[ni][1] = f2tf(Ks[c * 68 + ks * 8 + t4 + 4]);
        }
        #pragma unroll
        for (int mi = 0; mi < 4; mi++)
            #pragma unroll
            for (int ni = 0; ni < 4; ni++)
                mma8(acc[mi][ni], af[mi], bf[ni], acc[mi][ni]);
    }

    float* dst = S + (size_t)bh * TT * TT;
    #pragma unroll
    for (int mi = 0; mi < 4; mi++)
        #pragma unroll
        for (int ni = 0; ni < 4; ni++) {
            int r0 = q0 + wm + mi * 16 + g;
            int col = t0 + wn + ni * 8 + 2 * t4;
            *(float2*)&dst[(size_t)r0 * TT + col] = make_float2(acc[mi][ni][0], acc[mi][ni][1]);
            *(float2*)&dst[(size_t)(r0 + 8) * TT + col] = make_float2(acc[mi][ni][2], acc[mi][ni][3]);
        }
}

// ---------------- 4) fused bias + S-combine + mask + softmax -----------------
// CTA per q, 512 threads. 16 chunks of 64 t. Per chunk: cp.async pos_k + S,
// bias mma (2m x 8n warps), combine+mask+scale into Ss. Then smem softmax.
__global__ void __launch_bounds__(512)
bsm_kernel(const float* __restrict__ Qg, const float* __restrict__ PK,
           const int* __restrict__ mask, float* __restrict__ S)
{
    extern __shared__ float sm[];
    float* Ss = sm;                          // [32][SSTR]
    float* Qs = Ss + 32 * SSTR;              // [32][68]
    int*   Mk = (int*)(Qs + 32 * 68);        // [8][1024]  -- all 8 batches!
    float* Ps = (float*)(Mk + 8 * 1024);     // [2][64][68]
    float* Sg = Ps + 2 * 64 * 68;            // [2][32][68]
    int tid = threadIdx.x, w = tid >> 5, l = tid & 31, g = l >> 2, t4 = l & 3;
    int q = blockIdx.x;
    int wm_ = (w & 1) * 16, wn_ = (w >> 1) * 8;

    if (tid < 256) {
        int bh = tid >> 3, dg = (tid & 7) * 8;
        const float* src = Qg + ((size_t)bh * TT + q) * DKK + dg;
        *(float4*)&Qs[bh * 68 + dg]     = *(const float4*)(src);
        *(float4*)&Qs[bh * 68 + dg + 4] = *(const float4*)(src + 4);
    }
    #pragma unroll
    for (int j = 0; j < 4; j++) {            // mask: 8 batches x 256 int4 = 2048 chunks
        int ch = tid + 512 * j;
        int b_ = ch >> 8, t = (ch & 255) * 4;
        *(int4*)&Mk[b_ * 1024 + t] = *(const int4*)&mask[((size_t)b_ * TT + q) * TT + t];
    }

    auto load_chunk = [&](int buf, int c) {
        int t0 = c * 64;
        float* Pb = Ps + buf * 64 * 68;
        #pragma unroll
        for (int j = 0; j < 2; j++) {        // pos_k: 64 rows x 16 chunks
            int ch = tid + 512 * j;
            int row = ch >> 4, cc = ch & 15;
            cpa16(&Pb[row * 68 + cc * 4], PK + ((size_t)q * TT + t0 + row) * DKK + cc * 4);
        }
        float* Sb = Sg + buf * 32 * 68;
        {                                     // S: 32 bh rows x 16 chunks
            int row = tid >> 4, cc = tid & 15;
            cpa16(&Sb[row * 68 + cc * 4],
                  S + (size_t)row * TT * TT + (size_t)q * TT + t0 + cc * 4);
        }
        cp_commit();
    };

    load_chunk(0, 0);
    __syncthreads();

    for (int c = 0; c < 16; c++) {
        int buf = c & 1;
        cp_wait<0>();
        __syncthreads();
        if (c + 1 < 16) load_chunk(buf ^ 1, c + 1);
        const float* Pb = Ps + buf * 64 * 68;
        const float* Sb = Sg + buf * 32 * 68;

        float acc[4] = {0.f, 0.f, 0.f, 0.f};
        #pragma unroll
        for (int ks = 0; ks < 8; ks++) {
            unsigned af[4], bf[2];
            af[0] = f2tf(Qs[(wm_ + g    ) * 68 + ks * 8 + t4]);
            af[1] = f2tf(Qs[(wm_ + g + 8) * 68 + ks * 8 + t4]);
            af[2] = f2tf(Qs[(wm_ + g    ) * 68 + ks * 8 + t4 + 4]);
            af[3] = f2tf(Qs[(wm_ + g + 8) * 68 + ks * 8 + t4 + 4]);
            int cn = wn_ + g;
            bf[0] = f2tf(Pb[cn * 68 + ks * 8 + t4]);
            bf[1] = f2tf(Pb[cn * 68 + ks * 8 + t4 + 4]);
            mma8(acc, af, bf, acc);
        }
        int t0 = c * 64;
        int colL = wn_ + 2 * t4;
        #pragma unroll
        for (int rr = 0; rr < 2; rr++) {
            int bh = wm_ + g + rr * 8;
            int b_ = bh >> 2;
            #pragma unroll
            for (int cc2 = 0; cc2 < 2; cc2++) {
                int tl = colL + cc2;
                float sv = Sb[bh * 68 + tl];
                int m = Mk[b_ * 1024 + t0 + tl];
                float v = (m == 0) ? -FLT_MAX : (sv + acc[rr * 2 + cc2]) * 0.125f;
                Ss[bh * SSTR + t0 + tl] = v;
            }
        }
        __syncthreads();
    }

    // ---- softmax: warp w owns bh = 2w, 2w+1; values already masked+scaled ----
    #pragma unroll
    for (int bb = 0; bb < 2; bb++) {
        int bh = w * 2 + bb;
        float* srow = S + (size_t)bh * TT * TT + (size_t)q * TT;
        float* ssr  = Ss + bh * SSTR;

        float mx = -FLT_MAX;
        #pragma unroll
        for (int i = 0; i < 8; i++) {
            int t = 4 * (l + 32 * i);
            float4 v = *(const float4*)&ssr[t];
            mx = fmaxf(mx, fmaxf(fmaxf(v.x, v.y), fmaxf(v.z, v.w)));
        }
        #pragma unroll
        for (int o = 16; o > 0; o >>= 1)
            mx = fmaxf(mx, __shfl_xor_sync(0xffffffffu, mx, o));

        float sum = 0.f;
        #pragma unroll
        for (int i = 0; i < 8; i++) {
            int t = 4 * (l + 32 * i);
            float4 v = *(const float4*)&ssr[t];
            float4 p;
            p.x = (v.x == -FLT_MAX) ? 0.f : __expf(v.x - mx);
            p.y = (v.y == -FLT_MAX) ? 0.f : __expf(v.y - mx);
            p.z = (v.z == -FLT_MAX) ? 0.f : __expf(v.z - mx);
            p.w = (v.w == -FLT_MAX) ? 0.f : __expf(v.w - mx);
            *(float4*)&ssr[t] = p;
            sum += p.x + p.y + p.z + p.w;
        }
        #pragma unroll
        for (int o = 16; o > 0; o >>= 1)
            sum += __shfl_xor_sync(0xffffffffu, sum, o);
        float inv = (sum > 0.f) ? (1.f / sum) : 0.f;

        #pragma unroll
        for (int i = 0; i < 8; i++) {
            int t = 4 * (l + 32 * i);
            float4 v = *(const float4*)&ssr[t];
            float4 o;
            o.x = v.x * inv; o.y = v.y * inv; o.z = v.z * inv; o.w = v.w * inv;
            *(float4*)&srow[t] = o;
        }
    }
}

// ---------------- 5) tf32 AV: 256q x 64d, 512 threads, double buffered -------
__global__ void __launch_bounds__(512)
av_tf32(const float* __restrict__ P, const float* __restrict__ V, float* __restrict__ O)
{
    extern __shared__ float avsm[];
    float* Ps = avsm;                  // [2][256][68]
    float* Vs = avsm + 2 * 256 * 68;   // [2][64][72]
    int tid = threadIdx.x, w = tid >> 5, l = tid & 31, g = l >> 2, t4 = l & 3;
    int q0 = blockIdx.x * 256;
    int bh = blockIdx.y, b_ = bh >> 2, h = bh & 3;
    int wm = (w >> 1) * 32, wn = (w & 1) * 32;

    float acc[2][4][4];
    #pragma unroll
    for (int i = 0; i < 2; i++)
        #pragma unroll
        for (int j = 0; j < 4; j++)
            #pragma unroll
            for (int e = 0; e < 4; e++) acc[i][j][e] = 0.f;

    const float* Pb_g = P + (size_t)bh * TT * TT;
    const float* Vb_g = V + (size_t)bh * TT * DKK;

    auto load_stage = [&](int buf, int t0) {
        float* Pd = Ps + buf * 256 * 68;
        #pragma unroll
        for (int j = 0; j < 8; j++) {
            int ch = tid + 512 * j;
            int row = ch >> 4, c = ch & 15;
            cpa16(&Pd[row * 68 + c * 4], Pb_g + (size_t)(q0 + row) * TT + t0 + c * 4);
        }
        float* Vd = Vs + buf * 64 * 72;
        #pragma unroll
        for (int j = 0; j < 2; j++) {
            int ch = tid + 512 * j;
            int row = ch >> 4, c = ch & 15;
            cpa16(&Vd[row * 72 + c * 4], Vb_g + (size_t)(t0 + row) * DKK + c * 4);
        }
        cp_commit();
    };

    load_stage(0, 0);

    for (int it = 0; it < 16; it++) {
        int buf = it & 1;
        cp_wait<0>();
        __syncthreads();
        if (it + 1 < 16) load_stage(buf ^ 1, (it + 1) * 64);
        const float* Pd = Ps + buf * 256 * 68;
        const float* Vd = Vs + buf * 64 * 72;
        #pragma unroll
        for (int ks = 0; ks < 8; ks++) {
            unsigned af[2][4], bf[4][2];
            #pragma unroll
            for (int mi = 0; mi < 2; mi++) {
                int r = wm + mi * 16;
                af[mi][0] = f2tf(Pd[(r + g    ) * 68 + ks * 8 + t4]);
                af[mi][1] = f2tf(Pd[(r + g + 8) * 68 + ks * 8 + t4]);
                af[mi][2] = f2tf(Pd[(r + g    ) * 68 + ks * 8 + t4 + 4]);
                af[mi][3] = f2tf(Pd[(r + g + 8) * 68 + ks * 8 + t4 + 4]);
            }
            #pragma unroll
            for (int ni = 0; ni < 4; ni++) {
                int c = wn + ni * 8 + g;
                bf[ni][0] = f2tf(Vd[(ks * 8 + t4    ) * 72 + c]);
                bf[ni][1] = f2tf(Vd[(ks * 8 + t4 + 4) * 72 + c]);
            }
            #pragma unroll
            for (int mi = 0; mi < 2; mi++)
                #pragma unroll
                for (int ni = 0; ni < 4; ni++)
                    mma8(acc[mi][ni], af[mi], bf[ni], acc[mi][ni]);
        }
        __syncthreads();
    }

    #pragma unroll
    for (int mi = 0; mi < 2; mi++)
        #pragma unroll
        for (int ni = 0; ni < 4; ni++) {
            int qq = q0 + wm + mi * 16 + g;
            int d  = wn + ni * 8 + 2 * t4;
            *(float2*)&O[((size_t)b_ * TT + qq) * FF + h * DKK + d] =
                make_float2(acc[mi][ni][0], acc[mi][ni][1]);
            *(float2*)&O[((size_t)b_ * TT + qq + 8) * FF + h * DKK + d] =
                make_float2(acc[mi][ni][2], acc[mi][ni][3]);
        }
}

// ---------------- launch ------------------------------------------------------
extern "C" void kernel_launch(void* const* d_in, const int* in_sizes, int n_in,
                              void* d_out, int out_size)
{
    (void)in_sizes; (void)n_in; (void)out_size;
    const float* x     = (const float*)d_in[0];
    const float* q_in  = (const float*)d_in[1];
    const float* pos_k = (const float*)d_in[2];
    const int*   mask  = (const int*)  d_in[3];
    const float* ln_g  = (const float*)d_in[4];
    const float* ln_b  = (const float*)d_in[5];
    const float* Wq    = (const float*)d_in[6];
    const float* bq    = (const float*)d_in[7];
    const float* Wk    = (const float*)d_in[8];
    const float* bk    = (const float*)d_in[9];
    const float* Wv    = (const float*)d_in[10];
    const float* bv    = (const float*)d_in[11];
    const float* Wo    = (const float*)d_in[12];
    const float* bo    = (const float*)d_in[13];
    float* out = (float*)d_out;

    float *p_xn, *p_q, *p_k, *p_v, *p_s, *p_att;
    cudaGetSymbolAddress((void**)&p_xn,  g_xn);
    cudaGetSymbolAddress((void**)&p_q,   g_q);
    cudaGetSymbolAddress((void**)&p_k,   g_k);
    cudaGetSymbolAddress((void**)&p_v,   g_v);
    cudaGetSymbolAddress((void**)&p_s,   g_s);
    cudaGetSymbolAddress((void**)&p_att, g_att);

    static const int GEMM_SMEM = 3 * G_STAGE_F * 4;
    static const int QK_SMEM   = 2 * 128 * 68 * 4;
    static const int BSM_SMEM  = (32 * SSTR + 32 * 68 + 8 * 1024
                                  + 2 * 64 * 68 + 2 * 32 * 68) * 4;   // 225280
    static const int AV_SMEM   = (2 * 256 * 68 + 2 * 64 * 72) * 4;    // 176128
    cudaFuncSetAttribute(proj3_kernel,    cudaFuncAttributeMaxDynamicSharedMemorySize, GEMM_SMEM);
    cudaFuncSetAttribute(gemm_out_kernel, cudaFuncAttributeMaxDynamicSharedMemorySize, GEMM_SMEM);
    cudaFuncSetAttribute(qk_tf32,         cudaFuncAttributeMaxDynamicSharedMemorySize, QK_SMEM);
    cudaFuncSetAttribute(bsm_kernel,      cudaFuncAttributeMaxDynamicSharedMemorySize, BSM_SMEM);
    cudaFuncSetAttribute(av_tf32,         cudaFuncAttributeMaxDynamicSharedMemorySize, AV_SMEM);

    ln_kernel<<<NROWS, 256>>>(x, ln_g, ln_b, p_xn);

    dim3 gproj(FF / 64, NROWS / 128, 3);
    proj3_kernel<<<gproj, 256, GEMM_SMEM>>>(q_in, p_xn, Wq, bq, Wk, bk, Wv, bv,
                                            p_q, p_k, p_v);

    dim3 gqk(TT / 128, TT / 128, BHH);
    qk_tf32<<<gqk, 256, QK_SMEM>>>(p_q, p_k, p_s);

    bsm_kernel<<<TT, 512, BSM_SMEM>>>(p_q, pos_k, mask, p_s);

    dim3 gav(TT / 256, BHH);
    av_tf32<<<gav, 512, AV_SMEM>>>(p_s, p_v, p_att);

    dim3 gout(FF / 64, NROWS / 128);
    gemm_out_kernel<<<gout, 256, GEMM_SMEM>>>(p_att, Wo, bo, out);
}